// round 7
// baseline (speedup 1.0000x reference)
#include <cuda_runtime.h>
#include <cstdint>

// ---------------------------------------------------------------------------
// Problem constants
// ---------------------------------------------------------------------------
#define BATCH 64
#define SEQ   512
#define DIM   768
#define BD    (BATCH * DIM)          // 49152
#define R192  192
#define KDIM  1536
#define PREDK 2304

#define KS_FC1  24                   // 1536 = 24 * 64
#define KS_GATE 16                   // 1536 = 16 * 96
#define KS_PRED 12                   // 2304 = 12 * 192

#define FC1_MN  (R192 * 512)         // 98304
#define GATE_MN (R192 * 768)         // 147456
#define PRED_MN (BATCH * 512)        // 32768

// smem per worker: 2 stages x (As[32][68] + Bs[32][128])
#define AS_F     2176                // 32*68
#define BS_F     4096                // 32*128
#define STAGE_F  (AS_F + BS_F)       // 6272 floats
#define WORKER_F (2 * STAGE_F)       // 12544 floats
#define TOTAL_SMEM_B (4 * WORKER_F * 4)   // 200704 bytes

// ---------------------------------------------------------------------------
// Device scratch
// ---------------------------------------------------------------------------
__device__ float g_ent  [BATCH * PREDK];
__device__ float g_e    [3 * BD];              // entity state, in-place
__device__ float g_X1   [R192 * KDIM];         // fc1 input  [eA | eB]
__device__ float g_X2   [R192 * KDIM];         // gate input [u  | e ]
__device__ float g_pfc1 [KS_FC1  * FC1_MN];
__device__ float g_pgate[KS_GATE * GATE_MN];
__device__ float g_ppred[KS_PRED * PRED_MN];

__device__ unsigned int g_bar_count = 0;
__device__ unsigned int g_bar_gen   = 0;

// ---------------------------------------------------------------------------
// Helpers
// ---------------------------------------------------------------------------
__device__ __forceinline__ unsigned long long pack2(float x, float y) {
    unsigned long long r;
    asm("mov.b64 %0, {%1, %2};" : "=l"(r) : "f"(x), "f"(y));
    return r;
}
__device__ __forceinline__ void ffma2(unsigned long long& acc,
                                      unsigned long long a,
                                      unsigned long long b) {
    asm("fma.rn.f32x2 %0, %1, %2, %3;" : "=l"(acc) : "l"(a), "l"(b), "l"(acc));
}
__device__ __forceinline__ float2 unpack2(unsigned long long v) {
    float2 f;
    asm("mov.b64 {%0, %1}, %2;" : "=f"(f.x), "=f"(f.y) : "l"(v));
    return f;
}
__device__ __forceinline__ float sigmoidf(float x) {
    return 1.0f / (1.0f + expf(-x));
}
__device__ __forceinline__ float4 ldcg4(const float* p) {
    return __ldcg(reinterpret_cast<const float4*>(p));
}
__device__ __forceinline__ void stcg4(float* p, float4 v) {
    __stcg(reinterpret_cast<float4*>(p), v);
}
// cp.async: 16B global -> shared
__device__ __forceinline__ void cp16(uint32_t saddr, const float* gptr) {
    asm volatile("cp.async.ca.shared.global [%0], [%1], 16;"
                 :: "r"(saddr), "l"(gptr) : "memory");
}
__device__ __forceinline__ void cp_commit() {
    asm volatile("cp.async.commit_group;" ::: "memory");
}
template<int N> __device__ __forceinline__ void cp_wait() {
    asm volatile("cp.async.wait_group %0;" :: "n"(N) : "memory");
}
// per-worker (128-thread) named barrier: ids 1..4
__device__ __forceinline__ void wbar(int w) {
    asm volatile("bar.sync %0, 128;" :: "r"(w + 1) : "memory");
}

__device__ __forceinline__ unsigned int atom_add_release(unsigned int* p, unsigned int v) {
    unsigned int r;
    asm volatile("atom.release.gpu.add.u32 %0, [%1], %2;"
                 : "=r"(r) : "l"(p), "r"(v) : "memory");
    return r;
}
__device__ __forceinline__ unsigned int ld_acquire(unsigned int* p) {
    unsigned int r;
    asm volatile("ld.acquire.gpu.u32 %0, [%1];" : "=r"(r) : "l"(p) : "memory");
    return r;
}
__device__ __forceinline__ void st_release(unsigned int* p, unsigned int v) {
    asm volatile("st.release.gpu.u32 [%0], %1;" :: "l"(p), "r"(v) : "memory");
}

// Grid barrier over all resident blocks (512 threads each)
__device__ __forceinline__ void grid_sync() {
    __syncthreads();
    if (threadIdx.x == 0) {
        unsigned int gen = ld_acquire(&g_bar_gen);
        unsigned int t = atom_add_release(&g_bar_count, 1u);
        if (t == gridDim.x - 1u) {
            g_bar_count = 0u;
            st_release(&g_bar_gen, gen + 1u);
        } else {
            while (ld_acquire(&g_bar_gen) == gen) { __nanosleep(32); }
        }
    }
    __syncthreads();
}

// ---------------------------------------------------------------------------
// GEMM tile: C[64 x 128] = A[64 x kchunk] * W[kchunk x 128-of-N]
// Worker = 128 threads as (tm 0..7) x (tn 0..15); per-thread 8 rows x 8 cols.
// Cols per thread: {tn*4+j} and {64+tn*4+j} (conflict-free LDS.128).
// B tiles arrive via cp.async (2-stage double buffer); A via reg transpose.
// ---------------------------------------------------------------------------
__device__ void gemm_tile(int w, int wt, float* sbase, uint32_t sb32,
                          const float* __restrict__ A, int lda,
                          const float* __restrict__ W, int N,
                          float* __restrict__ Pout, int kchunk)
{
    const int tm = wt >> 4;          // 0..7
    const int tn = wt & 15;          // 0..15
    const int arow = wt >> 1;        // 0..63   (A loader)
    const int acb  = (wt & 1) * 16;  // 0 / 16
    const int brw = wt >> 2;         // 0..31   (B loader)
    const int bcc = (wt & 3) * 32;   // 0,32,64,96

    unsigned long long acc[4][8];
    #pragma unroll
    for (int i = 0; i < 4; i++)
        #pragma unroll
        for (int j = 0; j < 8; j++) acc[i][j] = 0ULL;

    const int T = kchunk >> 5;
    const float* Abase = A + (size_t)arow * lda + acb;
    const float* Wbase = W + (size_t)brw * N + bcc;
    const uint32_t bOff0 = sb32 + (AS_F + brw * 128 + bcc) * 4;

    wbar(w);                                  // prev smem users done

    // issue B0 -> stage0 ; load A0 regs
    #pragma unroll
    for (int j = 0; j < 8; j++) cp16(bOff0 + j * 16, Wbase + j * 4);
    cp_commit();
    float4 An[4];
    #pragma unroll
    for (int j = 0; j < 4; j++) An[j] = ldcg4(Abase + j * 4);
    // store A0 (transposed) -> stage0
    {
        const float* av = reinterpret_cast<const float*>(An);
        #pragma unroll
        for (int j = 0; j < 16; j++)
            sbase[(acb + j) * 68 + arow] = av[j];
    }
    // issue B1 -> stage1 ; load A1 regs
    if (T > 1) {
        uint32_t d = bOff0 + STAGE_F * 4;
        const float* s = Wbase + 32 * N;
        #pragma unroll
        for (int j = 0; j < 8; j++) cp16(d + j * 16, s + j * 4);
        cp_commit();
        #pragma unroll
        for (int j = 0; j < 4; j++) An[j] = ldcg4(Abase + 32 + j * 4);
        cp_wait<1>();
    } else {
        cp_wait<0>();
    }
    wbar(w);

    int p = 0;
    for (int t = 0; t < T; t++) {
        const float* As = sbase + p * STAGE_F;
        const float* Bs = As + AS_F;
        #pragma unroll
        for (int kk = 0; kk < 32; kk++) {
            float4 a0 = *(const float4*)&As[kk * 68 + tm * 8];
            float4 a1 = *(const float4*)&As[kk * 68 + tm * 8 + 4];
            float4 b0 = *(const float4*)&Bs[kk * 128 + tn * 4];
            float4 b1 = *(const float4*)&Bs[kk * 128 + 64 + tn * 4];
            unsigned long long ap0 = pack2(a0.x, a0.y);
            unsigned long long ap1 = pack2(a0.z, a0.w);
            unsigned long long ap2 = pack2(a1.x, a1.y);
            unsigned long long ap3 = pack2(a1.z, a1.w);
            unsigned long long bd[8];
            bd[0] = pack2(b0.x, b0.x); bd[1] = pack2(b0.y, b0.y);
            bd[2] = pack2(b0.z, b0.z); bd[3] = pack2(b0.w, b0.w);
            bd[4] = pack2(b1.x, b1.x); bd[5] = pack2(b1.y, b1.y);
            bd[6] = pack2(b1.z, b1.z); bd[7] = pack2(b1.w, b1.w);
            #pragma unroll
            for (int n = 0; n < 8; n++) {
                ffma2(acc[0][n], ap0, bd[n]);
                ffma2(acc[1][n], ap1, bd[n]);
                ffma2(acc[2][n], ap2, bd[n]);
                ffma2(acc[3][n], ap3, bd[n]);
            }
        }

        if (t + 1 < T) {
            // store prefetched A[t+1] into the other stage
            float* Aq = sbase + (1 - p) * STAGE_F;
            const float* av = reinterpret_cast<const float*>(An);
            #pragma unroll
            for (int j = 0; j < 16; j++)
                Aq[(acb + j) * 68 + arow] = av[j];
            cp_wait<0>();                     // B[t+1] arrived
            wbar(w);                          // everyone done with stage p
            if (t + 2 < T) {
                uint32_t d = bOff0 + p * STAGE_F * 4;
                const float* s = Wbase + (size_t)(t + 2) * 32 * N;
                #pragma unroll
                for (int j = 0; j < 8; j++) cp16(d + j * 16, s + j * 4);
                cp_commit();
                #pragma unroll
                for (int j = 0; j < 4; j++)
                    An[j] = ldcg4(Abase + (t + 2) * 32 + j * 4);
            }
            p ^= 1;
        }
    }

    // epilogue: 8 rows x (2 groups of 4 cols)
    #pragma unroll
    for (int mm = 0; mm < 4; mm++) {
        float2 vA0 = unpack2(acc[mm][0]);
        float2 vA1 = unpack2(acc[mm][1]);
        float2 vA2 = unpack2(acc[mm][2]);
        float2 vA3 = unpack2(acc[mm][3]);
        float2 vB0 = unpack2(acc[mm][4]);
        float2 vB1 = unpack2(acc[mm][5]);
        float2 vB2 = unpack2(acc[mm][6]);
        float2 vB3 = unpack2(acc[mm][7]);
        int r0 = tm * 8 + 2 * mm;
        float* row0 = Pout + (size_t)r0 * N;
        float* row1 = row0 + N;
        stcg4(row0 + tn * 4,      make_float4(vA0.x, vA1.x, vA2.x, vA3.x));
        stcg4(row0 + 64 + tn * 4, make_float4(vB0.x, vB1.x, vB2.x, vB3.x));
        stcg4(row1 + tn * 4,      make_float4(vA0.y, vA1.y, vA2.y, vA3.y));
        stcg4(row1 + 64 + tn * 4, make_float4(vB0.y, vB1.y, vB2.y, vB3.y));
    }
}

// X1 slot tables. Pairs: p0=[e1|e2], p1=[e0|e2], p2=[e0|e1]
__device__ __constant__ int D1ROW[3] = {1, 0, 0};
__device__ __constant__ int D1OFF[3] = {0, 0, 768};
__device__ __constant__ int D2ROW[3] = {2, 2, 1};
__device__ __constant__ int D2OFF[3] = {0, 768, 768};

// ---------------------------------------------------------------------------
// Phase jobs (per 128-thread worker)
// ---------------------------------------------------------------------------
__device__ void maxpool_job(int w, int wt, float* sb, int bk,
                            const float* __restrict__ enc,
                            const int* __restrict__ ep,
                            const float* __restrict__ projW,
                            const float* __restrict__ projb,
                            float* __restrict__ out_score)
{
    float* red = sb;
    int b = bk / 3, k = bk - b * 3;
    int s0 = ep[bk * 2 + 0];
    int s1 = ep[bk * 2 + 1];

    float m[6];
    #pragma unroll
    for (int q = 0; q < 6; q++) m[q] = -1e30f;
    const float* base = enc + (size_t)b * SEQ * DIM;
    for (int s = s0; s <= s1; s++) {
        const float* row = base + s * DIM;
        #pragma unroll
        for (int q = 0; q < 6; q++)
            m[q] = fmaxf(m[q], __ldg(row + wt + q * 128));
    }

    size_t x1a = (size_t)(D1ROW[k] * 64 + b) * KDIM + D1OFF[k];
    size_t x1b = (size_t)(D2ROW[k] * 64 + b) * KDIM + D2OFF[k];
    size_t x2r = (size_t)(k * 64 + b) * KDIM + 768;
    size_t er  = (size_t)(k * 64 + b) * DIM;
    size_t eno = (size_t)b * PREDK + k * DIM;

    float loc = 0.0f;
    #pragma unroll
    for (int q = 0; q < 6; q++) {
        int d = wt + q * 128;
        __stcg(g_ent + eno + d, m[q]);
        __stcg(g_e   + er  + d, m[q]);
        __stcg(g_X1  + x1a + d, m[q]);
        __stcg(g_X1  + x1b + d, m[q]);
        __stcg(g_X2  + x2r + d, m[q]);
        loc += m[q] * projW[d];
    }

    wbar(w);
    red[wt] = loc;
    wbar(w);
    for (int off = 64; off > 0; off >>= 1) {
        if (wt < off) red[wt] += red[wt + off];
        wbar(w);
    }
    if (wt == 0) out_score[bk] = sigmoidf(red[0] + projb[0]);
    wbar(w);
}

__device__ void finish1_job(int w, int wt, float* sb, int r,
                            const float* __restrict__ b1,
                            const float* __restrict__ W2, const float* __restrict__ b2,
                            const float* __restrict__ ArW, const float* __restrict__ Arb)
{
    float* sh_h = sb;                  // 512
    float* red  = sb + 512;            // 5*128
    float* sh_s = sb + 512 + 640;      // 8

    wbar(w);
    for (int j = wt; j < 512; j += 128) {
        float s = b1[j];
        #pragma unroll
        for (int z = 0; z < KS_FC1; z++)
            s += __ldcg(g_pfc1 + (size_t)z * FC1_MN + r * 512 + j);
        sh_h[j] = fmaxf(s, 0.0f);
    }
    wbar(w);

    float ps[5] = {0, 0, 0, 0, 0};
    for (int j = wt; j < 512; j += 128) {
        float h = sh_h[j];
        #pragma unroll
        for (int c = 0; c < 5; c++) ps[c] += h * W2[j * 5 + c];
    }
    #pragma unroll
    for (int c = 0; c < 5; c++) red[c * 128 + wt] = ps[c];
    wbar(w);
    for (int off = 64; off > 0; off >>= 1) {
        if (wt < off) {
            #pragma unroll
            for (int c = 0; c < 5; c++) red[c * 128 + wt] += red[c * 128 + wt + off];
        }
        wbar(w);
    }
    if (wt < 5) sh_s[wt] = sigmoidf(red[wt * 128] + b2[wt]);
    wbar(w);

    float s0 = sh_s[0], s1 = sh_s[1], s2 = sh_s[2], s3 = sh_s[3], s4 = sh_s[4];
    const float* epv = g_e + (size_t)r * DIM;
    float* up = g_X2 + (size_t)r * KDIM;          // u -> left half of X2
    for (int d = wt; d < DIM; d += 128) {
        float a = Arb[d] + s0 * ArW[d] + s1 * ArW[DIM + d] + s2 * ArW[2 * DIM + d]
                + s3 * ArW[3 * DIM + d] + s4 * ArW[4 * DIM + d];
        __stcg(up + d, a * __ldcg(epv + d));
    }
}

__device__ void pred_finish_job(int w, int wt, float* sb, int b,
                                const float* __restrict__ b1,
                                const float* __restrict__ W2,
                                const float* __restrict__ b2,
                                float* __restrict__ rel_out)
{
    float* sh_h = sb;
    float* red  = sb + 512;

    wbar(w);
    for (int j = wt; j < 512; j += 128) {
        float s = b1[j];
        #pragma unroll
        for (int z = 0; z < KS_PRED; z++)
            s += __ldcg(g_ppred + (size_t)z * PRED_MN + b * 512 + j);
        sh_h[j] = fmaxf(s, 0.0f);
    }
    wbar(w);

    float ps[5] = {0, 0, 0, 0, 0};
    for (int j = wt; j < 512; j += 128) {
        float h = sh_h[j];
        #pragma unroll
        for (int c = 0; c < 5; c++) ps[c] += h * W2[j * 5 + c];
    }
    #pragma unroll
    for (int c = 0; c < 5; c++) red[c * 128 + wt] = ps[c];
    wbar(w);
    for (int off = 64; off > 0; off >>= 1) {
        if (wt < off) {
            #pragma unroll
            for (int c = 0; c < 5; c++) red[c * 128 + wt] += red[c * 128 + wt + off];
        }
        wbar(w);
    }
    if (wt < 5) rel_out[b * 5 + wt] = red[wt * 128] + b2[wt];
}

// ---------------------------------------------------------------------------
// Persistent fused kernel: 512 threads = four 128-thread workers
// ---------------------------------------------------------------------------
__global__ void __launch_bounds__(512, 1)
fused_kernel(const float* __restrict__ enc, const int* __restrict__ ep,
             const float* __restrict__ ArW, const float* __restrict__ Arb,
             const float* __restrict__ VrW1, const float* __restrict__ Vrb1,
             const float* __restrict__ VrW2, const float* __restrict__ Vrb2,
             const float* __restrict__ gateW, const float* __restrict__ gateb,
             const float* __restrict__ predW1, const float* __restrict__ predb1,
             const float* __restrict__ predW2, const float* __restrict__ predb2,
             const float* __restrict__ projW, const float* __restrict__ projb,
             float* __restrict__ out_rel, float* __restrict__ out_score,
             float* __restrict__ out_final)
{
    extern __shared__ __align__(16) float smem_u[];

    const int w  = threadIdx.x >> 7;       // worker slot 0..3
    const int wt = threadIdx.x & 127;
    float* sbase = smem_u + w * WORKER_F;
    const uint32_t sb32 =
        (uint32_t)__cvta_generic_to_shared(sbase);

    const int nb = gridDim.x;
    const int wid     = w * nb + blockIdx.x;   // block-major striping
    const int wstride = 4 * nb;                // 592 workers

    // ---- Phase 0: span max-pool (+ scores, X1/X2 init) ----
    for (int job = wid; job < R192; job += wstride)
        maxpool_job(w, wt, sbase, job, enc, ep, projW, projb, out_score);
    grid_sync();

    for (int it = 0; it < 5; it++) {
        // ---- P1: fc1 GEMM partials (288) + pred GEMM (48, iter 0) ----
        int nj = (it == 0) ? (288 + 48) : 288;
        for (int job = wid; job < nj; job += wstride) {
            if (job < 288) {
                int z = job / 12, rem = job % 12;
                int m0 = (rem >> 2) * 64, n0 = (rem & 3) * 128;
                int k0 = z * 64;
                gemm_tile(w, wt, sbase, sb32,
                          g_X1 + (size_t)m0 * KDIM + k0, KDIM,
                          VrW1 + (size_t)k0 * 512 + n0, 512,
                          g_pfc1 + (size_t)z * FC1_MN + m0 * 512 + n0, 64);
            } else {
                int j = job - 288;                 // 0..47
                int z = j >> 2, n0 = (j & 3) * 128;
                int k0 = z * 192;
                gemm_tile(w, wt, sbase, sb32,
                          g_ent + k0, PREDK,
                          predW1 + (size_t)k0 * 512 + n0, 512,
                          g_ppred + (size_t)z * PRED_MN + n0, 192);
            }
        }
        grid_sync();

        // ---- P2: fc1 finish -> u (+ pred finish on iter 0) ----
        nj = (it == 0) ? 256 : 192;
        for (int job = wid; job < nj; job += wstride) {
            if (job < 192) finish1_job(w, wt, sbase, job, Vrb1, VrW2, Vrb2, ArW, Arb);
            else           pred_finish_job(w, wt, sbase, job - 192,
                                           predb1, predW2, predb2, out_rel);
        }
        grid_sync();

        // ---- P3: gate GEMM partials (288) ----
        for (int job = wid; job < 288; job += wstride) {
            int z = job / 18, rem = job % 18;
            int m0 = (rem / 6) * 64, n0 = (rem % 6) * 128;
            int k0 = z * 96;
            gemm_tile(w, wt, sbase, sb32,
                      g_X2 + (size_t)m0 * KDIM + k0, KDIM,
                      gateW + (size_t)k0 * 768 + n0, 768,
                      g_pgate + (size_t)z * GATE_MN + m0 * 768 + n0, 96);
        }
        grid_sync();

        // ---- P4: gate blend; in-place e update + X1/X2 scatter ----
        bool last = (it == 4);
        int tg = blockIdx.x * 512 + threadIdx.x;
        for (int q = tg; q < GATE_MN / 4; q += nb * 512) {
            int idx = q * 4;
            int r = idx / 768, n = idx - r * 768;
            int p = r >> 6, b = r & 63;
            float4 s = *(const float4*)(gateb + n);
            #pragma unroll
            for (int z = 0; z < KS_GATE; z++) {
                float4 pv = ldcg4(g_pgate + (size_t)z * GATE_MN + idx);
                s.x += pv.x; s.y += pv.y; s.z += pv.z; s.w += pv.w;
            }
            float4 uv = ldcg4(g_X2 + (size_t)r * KDIM + n);   // u (left half)
            float4 ev = ldcg4(g_e + idx);
            float4 res; float gg;
            gg = sigmoidf(s.x); res.x = gg * ev.x + (1.0f - gg) * uv.x;
            gg = sigmoidf(s.y); res.y = gg * ev.y + (1.0f - gg) * uv.y;
            gg = sigmoidf(s.z); res.z = gg * ev.z + (1.0f - gg) * uv.z;
            gg = sigmoidf(s.w); res.w = gg * ev.w + (1.0f - gg) * uv.w;
            if (last) {
                *(float4*)(out_final + (size_t)b * PREDK + p * DIM + n) = res;
            } else {
                stcg4(g_e + idx, res);
                stcg4(g_X2 + (size_t)r * KDIM + 768 + n, res);
                stcg4(g_X1 + (size_t)(D1ROW[p] * 64 + b) * KDIM + D1OFF[p] + n, res);
                stcg4(g_X1 + (size_t)(D2ROW[p] * 64 + b) * KDIM + D2OFF[p] + n, res);
            }
        }
        if (!last) grid_sync();
    }
}

// ---------------------------------------------------------------------------
// Launcher
// ---------------------------------------------------------------------------
extern "C" void kernel_launch(void* const* d_in, const int* in_sizes, int n_in,
                              void* d_out, int out_size)
{
    const float* encoding = (const float*)d_in[0];
    const int*   ent_pos  = (const int*)  d_in[1];
    const float* Ar_W     = (const float*)d_in[2];
    const float* Ar_b     = (const float*)d_in[3];
    const float* Vr_W1    = (const float*)d_in[4];
    const float* Vr_b1    = (const float*)d_in[5];
    const float* Vr_W2    = (const float*)d_in[6];
    const float* Vr_b2    = (const float*)d_in[7];
    const float* gate_W   = (const float*)d_in[8];
    const float* gate_b   = (const float*)d_in[9];
    const float* pred_W1  = (const float*)d_in[10];
    const float* pred_b1  = (const float*)d_in[11];
    const float* pred_W2  = (const float*)d_in[12];
    const float* pred_b2  = (const float*)d_in[13];
    const float* proj_W   = (const float*)d_in[14];
    const float* proj_b   = (const float*)d_in[15];

    float* out = (float*)d_out;
    float* out_rel   = out;              // (64,5)
    float* out_score = out + 320;        // (64,3)
    float* out_final = out + 512;        // (64,3,768)

    int dev = 0;
    cudaGetDevice(&dev);
    int sms = 148;
    cudaDeviceGetAttribute(&sms, cudaDevAttrMultiProcessorCount, dev);

    cudaFuncSetAttribute(fused_kernel,
                         cudaFuncAttributeMaxDynamicSharedMemorySize,
                         TOTAL_SMEM_B);

    fused_kernel<<<sms, 512, TOTAL_SMEM_B>>>(
        encoding, ent_pos, Ar_W, Ar_b,
        Vr_W1, Vr_b1, Vr_W2, Vr_b2,
        gate_W, gate_b,
        pred_W1, pred_b1, pred_W2, pred_b2,
        proj_W, proj_b,
        out_rel, out_score, out_final);

    (void)in_sizes; (void)n_in; (void)out_size;
}